// round 7
// baseline (speedup 1.0000x reference)
#include <cuda_runtime.h>
#include <math.h>

#define EPSF 1e-9f
#define MAXF 4096
#define MAXB 8
#define FCAP 1024
#define MAXBV 2048

// fa = (A1,B1,C1,A2), fb = (B2,C2,Az,Bz), fc = (Cz,1/z0,1/z1,1/z2), cz = Cz
// C1 NaN-poisoned when invalid/backface -> culled at the tile test.
__device__ float4 g_fa[MAXB * MAXF];
__device__ float4 g_fb[MAXB * MAXF];
__device__ float4 g_fc[MAXB * MAXF];
__device__ float  g_cz[MAXB * MAXF];
__device__ float4 g_tex4[MAXF * 6];
__device__ float  g_part[8192];
__device__ int    g_cnt = 0;

__global__ void prep_kernel(const float* __restrict__ verts,
                            const int*   __restrict__ faces,
                            const float* __restrict__ Kmat,
                            const float* __restrict__ Rmat,
                            const float* __restrict__ tvec,
                            const float* __restrict__ textures,
                            int B, int V, int F, int S) {
    __shared__ float sv[MAXBV * 3];

    int idx = blockIdx.x * blockDim.x + threadIdx.x;
    int stride = gridDim.x * blockDim.x;

    const bool faceblock = (blockIdx.x * blockDim.x < B * F);
    const bool use_sv = faceblock && (B * V <= MAXBV);
    if (use_sv) {
        int n = B * V * 3;
        for (int i = threadIdx.x; i < n; i += blockDim.x) sv[i] = verts[i];
        __syncthreads();
    }

    // tex = tanh(textures[0]), float4-vectorized
    int texN4 = F * 6;
    const float4* t4 = (const float4*)textures;
    for (int i = idx; i < texN4; i += stride) {
        float4 v = t4[i];
        g_tex4[i] = make_float4(tanhf(v.x), tanhf(v.y), tanhf(v.z), tanhf(v.w));
    }

    if (idx >= B * F) return;
    int b = idx / F;
    int f = idx - b * F;

    const float* Rb = Rmat + b * 9;
    const float* Kb = Kmat + b * 9;
    const float* tb = tvec + b * 3;

    float xs[3], ys[3], zs[3];
#pragma unroll
    for (int vi = 0; vi < 3; vi++) {
        int vid = faces[(b * F + f) * 3 + vi];
        const float* p = use_sv ? (sv + ((size_t)b * V + vid) * 3)
                                : (verts + ((size_t)b * V + vid) * 3);
        float px = p[0], py = p[1], pz = p[2];
        float vx = Rb[0] * px + Rb[1] * py + Rb[2] * pz + tb[0];
        float vy = Rb[3] * px + Rb[4] * py + Rb[5] * pz + tb[1];
        float vz = Rb[6] * px + Rb[7] * py + Rb[8] * pz + tb[2];
        float xh = vx / (vz + EPSF);
        float yh = vy / (vz + EPSF);
        float u  = Kb[0] * xh + Kb[1] * yh + Kb[2];
        float pv = Kb[3] * xh + Kb[4] * yh + Kb[5];
        float v  = (float)S - pv;
        u = 2.0f * (u - 0.5f * (float)S) / (float)S;
        v = 2.0f * (v - 0.5f * (float)S) / (float)S;
        xs[vi] = u; ys[vi] = v; zs[vi] = vz;
    }

    float e1x = xs[1] - xs[0], e1y = ys[1] - ys[0];
    float e2x = xs[2] - xs[0], e2y = ys[2] - ys[0];
    float den = e1x * e2y - e2x * e1y;
    bool valid = fabsf(den) > 1e-8f;
    float dens = valid ? den : 1.0f;
    bool front = fminf(zs[0], fminf(zs[1], zs[2])) > EPSF;
    float rden = 1.0f / dens;

    float A1 =  e2y * rden;
    float B1 = -e2x * rden;
    float C1 = (ys[0] * e2x - xs[0] * e2y) * rden;
    float A2 = -e1y * rden;
    float B2 =  e1x * rden;
    float C2 = (xs[0] * e1y - ys[0] * e1x) * rden;

    float iz0 = 1.0f / zs[0], iz1 = 1.0f / zs[1], iz2 = 1.0f / zs[2];
    float d1 = iz1 - iz0, d2 = iz2 - iz0;
    float Az = A1 * d1 + A2 * d2;
    float Bz = B1 * d1 + B2 * d2;
    float Cz = iz0 + C1 * d1 + C2 * d2;

    if (!(valid && front)) C1 = __int_as_float(0x7FC00000);  // NaN

    g_fa[idx] = make_float4(A1, B1, C1, A2);
    g_fb[idx] = make_float4(B2, C2, Az, Bz);
    g_fc[idx] = make_float4(Cz, iz0, iz1, iz2);
    g_cz[idx] = Cz;
}

// block (8,16,4) = 512 threads = 16 warps; tile = 16x16 px;
// each thread: 2 adjacent x-pixels, 1 of 4 face slices.
// __launch_bounds__(512,4): cap regs at 32 -> 4 blocks/SM -> single wave.
__global__ void __launch_bounds__(512, 4)
raster_kernel(const float* __restrict__ image_ref,
              float* __restrict__ out,
              int B, int F, int S) {
    __shared__ int    slist[FCAP];
    __shared__ float4 sa[FCAP];
    __shared__ float4 sb[FCAP];
    __shared__ float  sc[FCAP];
    __shared__ int    swcnt[16];
    __shared__ float  swred[16];
    __shared__ float  smiv[3 * 256];
    __shared__ int    smfc[3 * 256];
    __shared__ int    slast;

    const int b     = blockIdx.z;
    const int slice = threadIdx.z;
    const int pix   = threadIdx.y * 8 + threadIdx.x;
    const int tid   = slice * 128 + pix;
    const int warp  = tid >> 5;
    const int lane  = tid & 31;
    const int x0    = blockIdx.x * 16 + threadIdx.x * 2;
    const int y     = blockIdx.y * 16 + threadIdx.y;
    const float invS = 1.0f / (float)S;
    const float step = 2.0f * invS;
    const float py  = (2.0f * (float)y  + 1.0f - (float)S) * invS;
    const float pxA = (2.0f * (float)x0 + 1.0f - (float)S) * invS;
    const float pxB = pxA + step;
    const bool activeA = (x0 < S) && (y < S);
    const bool activeB = (x0 + 1 < S) && (y < S);

    const float cxc = (2.0f * ((float)(blockIdx.x * 16) + 7.5f) + 1.0f - (float)S) * invS;
    const float cyc = (2.0f * ((float)(blockIdx.y * 16) + 7.5f) + 1.0f - (float)S) * invS;
    const float hw  = 15.0f * invS;
    const float hh  = 15.0f * invS;

    const float4* fa_g = g_fa + (size_t)b * F;
    const float4* fb_g = g_fb + (size_t)b * F;
    const float4* fc_g = g_fc + (size_t)b * F;
    const float*  cz_g = g_cz + (size_t)b * F;

    // fused exact-halfplane cull + ordered compaction + staging (512 wide)
    int cnt = 0;
    for (int base = 0; base < F; base += 512) {
        int f = base + tid;
        bool ok = false;
        float4 fa, fb;
        if (f < F) {
            fa = fa_g[f];
            fb = fb_g[f];
            float w1c = fmaf(fa.x, cxc, fmaf(fa.y, cyc, fa.z));
            float w2c = fmaf(fa.w, cxc, fmaf(fb.x, cyc, fb.y));
            float r1  = fmaf(fabsf(fa.x), hw, fabsf(fa.y) * hh);
            float r2  = fmaf(fabsf(fa.w), hw, fabsf(fb.x) * hh);
            float a0  = fa.x + fa.w, b0 = fa.y + fb.x;
            float w0c = 1.0f - w1c - w2c;
            float r0  = fmaf(fabsf(a0), hw, fabsf(b0) * hh);
            ok = (w1c + r1 >= 0.0f) && (w2c + r2 >= 0.0f) && (w0c + r0 >= 0.0f);
        }
        unsigned m = __ballot_sync(0xffffffffu, ok);
        int lanePfx = __popc(m & ((1u << lane) - 1u));
        if (lane == 0) swcnt[warp] = __popc(m);
        __syncthreads();
        int wbase = cnt;
#pragma unroll
        for (int w = 0; w < 16; w++) {
            int c = swcnt[w];
            if (w < warp) wbase += c;
            cnt += c;
        }
        if (ok) {
            int pos = wbase + lanePfx;
            slist[pos] = f;
            sa[pos] = fa;
            sb[pos] = fb;
            sc[pos] = cz_g[f];
        }
        __syncthreads();
    }
    const int nf = cnt;

    // each slice scans faces i ≡ slice (mod 4); 2 pixels per thread
    float bivA = EPSF, bivB = EPSF;
    int   biA = -1,   biB = -1;
#pragma unroll 4
    for (int i = slice; i < nf; i += 4) {
        const float4 fa = sa[i];
        const float4 fb = sb[i];
        const float  cz = sc[i];
        float t1 = fmaf(fa.y, py, fa.z);
        float t2 = fmaf(fb.x, py, fb.y);
        float tz = fmaf(fb.w, py, cz);
        float w1A = fmaf(fa.x, pxA, t1), w1B = fmaf(fa.x, pxB, t1);
        float w2A = fmaf(fa.w, pxA, t2), w2B = fmaf(fa.w, pxB, t2);
        float ivA = fmaf(fb.z, pxA, tz), ivB = fmaf(fb.z, pxB, tz);
        float sA = w1A + w2A, sB = w1B + w2B;
        if (w1A >= 0.0f && w2A >= 0.0f && sA <= 1.0f && ivA > bivA) {
            bivA = ivA; biA = i;
        }
        if (w1B >= 0.0f && w2B >= 0.0f && sB <= 1.0f && ivB > bivB) {
            bivB = ivB; biB = i;
        }
    }
    int bfA = (biA >= 0) ? slist[biA] : -1;
    int bfB = (biB >= 0) ? slist[biB] : -1;

    // deterministic 4-way merge: max invz, ties -> smaller face id
    if (slice > 0) {
        int o = (slice - 1) * 256 + pix * 2;
        smiv[o]     = bivA; smfc[o]     = bfA;
        smiv[o + 1] = bivB; smfc[o + 1] = bfB;
    }
    __syncthreads();
    if (slice == 0) {
#pragma unroll
        for (int s = 0; s < 3; s++) {
            int o = s * 256 + pix * 2;
            float ivc = smiv[o];     int fc0 = smfc[o];
            if (fc0 >= 0 && (bfA < 0 || ivc > bivA ||
                             (ivc == bivA && fc0 < bfA))) { bivA = ivc; bfA = fc0; }
            float ivd = smiv[o + 1]; int fc1 = smfc[o + 1];
            if (fc1 >= 0 && (bfB < 0 || ivd > bivB ||
                             (ivd == bivB && fc1 < bfB))) { bivB = ivd; bfB = fc1; }
        }
    }

    // epilogue on slice 0: perspective-correct trilinear texture + sq error
    float lsum = 0.0f;
    if (slice == 0) {
#pragma unroll
        for (int sub = 0; sub < 2; sub++) {
            const bool act = sub ? activeB : activeA;
            if (!act) continue;
            const float px = sub ? pxB : pxA;
            const int   f  = sub ? bfB : bfA;
            const int   xx = x0 + sub;
            float col[3] = {0.0f, 0.0f, 0.0f};
            if (f >= 0) {
                const float4 fa = fa_g[f];
                const float4 fb = fb_g[f];
                const float4 fc = fc_g[f];
                float w1 = fmaf(fa.x, px, fmaf(fa.y, py, fa.z));
                float w2 = fmaf(fa.w, px, fmaf(fb.x, py, fb.y));
                float iv = fmaf(fb.z, px, fmaf(fb.w, py, fc.x));
                float w0 = 1.0f - w1 - w2;
                float iz = fmaxf(iv, EPSF);
                float r  = 1.0f / iz;
                float wp0 = __saturatef(w0 * fc.y * r);
                float wp1 = __saturatef(w1 * fc.z * r);
                float wp2 = __saturatef(w2 * fc.w * r);
                float q0 = 1.0f - wp0, q1 = 1.0f - wp1, q2 = 1.0f - wp2;
                // W[i*4+j*2+k] = a0[i]*a1[j]*a2[k]
                float W[8];
                W[0] = q0 * q1 * q2;  W[1] = q0 * q1 * wp2;
                W[2] = q0 * wp1 * q2; W[3] = q0 * wp1 * wp2;
                W[4] = wp0 * q1 * q2; W[5] = wp0 * q1 * wp2;
                W[6] = wp0 * wp1 * q2; W[7] = wp0 * wp1 * wp2;
                // accumulate channels directly from texels (no tv[] buffer)
#pragma unroll
                for (int q = 0; q < 6; q++) {
                    float4 v = g_tex4[f * 6 + q];
                    col[(q * 4 + 0) % 3] += v.x * W[(q * 4 + 0) / 3];
                    col[(q * 4 + 1) % 3] += v.y * W[(q * 4 + 1) / 3];
                    col[(q * 4 + 2) % 3] += v.z * W[(q * 4 + 2) / 3];
                    col[(q * 4 + 3) % 3] += v.w * W[(q * 4 + 3) / 3];
                }
            }
            float rv0 = image_ref[((size_t)(b * 3 + 0) * S + y) * S + xx];
            float rv1 = image_ref[((size_t)(b * 3 + 1) * S + y) * S + xx];
            float rv2 = image_ref[((size_t)(b * 3 + 2) * S + y) * S + xx];
            float d0 = col[0] - rv0, d1 = col[1] - rv1, d2 = col[2] - rv2;
            lsum += d0 * d0 + d1 * d1 + d2 * d2;
        }
    }

    // deterministic block reduction
#pragma unroll
    for (int o = 16; o > 0; o >>= 1)
        lsum += __shfl_down_sync(0xffffffffu, lsum, o);
    if (lane == 0) swred[warp] = lsum;
    __syncthreads();

    const int nb = gridDim.x * gridDim.y * gridDim.z;
    const int bid = blockIdx.z * gridDim.x * gridDim.y
                  + blockIdx.y * gridDim.x + blockIdx.x;
    if (tid == 0) {
        float s = 0.0f;
#pragma unroll
        for (int w = 0; w < 16; w++) s += swred[w];
        g_part[bid] = s;
        __threadfence();
        int t = atomicAdd(&g_cnt, 1);
        slast = (t == nb - 1);
    }
    __syncthreads();

    // last block: deterministic fixed-order final reduction
    if (slast) {
        float s = 0.0f;
        for (int i = tid; i < nb; i += 512) s += g_part[i];
#pragma unroll
        for (int o = 16; o > 0; o >>= 1)
            s += __shfl_down_sync(0xffffffffu, s, o);
        if (lane == 0) swred[warp] = s;
        __syncthreads();
        if (tid == 0) {
            float tot = 0.0f;
#pragma unroll
            for (int w = 0; w < 16; w++) tot += swred[w];
            out[0] = tot;
            g_cnt = 0;   // reset for next graph replay
        }
    }
}

extern "C" void kernel_launch(void* const* d_in, const int* in_sizes, int n_in,
                              void* d_out, int out_size) {
    const float* vertices  = (const float*)d_in[0];
    const int*   faces     = (const int*)  d_in[1];
    const float* Kmat      = (const float*)d_in[2];
    const float* Rmat      = (const float*)d_in[3];
    const float* tvec      = (const float*)d_in[4];
    const float* textures  = (const float*)d_in[5];
    const float* image_ref = (const float*)d_in[6];

    int B = in_sizes[2] / 9;
    int V = in_sizes[0] / (3 * B);
    int F = in_sizes[1] / (3 * B);
    int ss = in_sizes[6] / (3 * B);
    int S = (int)(sqrt((double)ss) + 0.5);

    float* out = (float*)d_out;

    int prepN = (B * F > F * 6) ? B * F : F * 6;
    prep_kernel<<<(prepN + 255) / 256, 256>>>(vertices, faces, Kmat, Rmat,
                                              tvec, textures, B, V, F, S);

    dim3 blk(8, 16, 4);
    dim3 grd((S + 15) / 16, (S + 15) / 16, B);
    raster_kernel<<<grd, blk>>>(image_ref, out, B, F, S);
}

// round 8
// speedup vs baseline: 1.1620x; 1.1620x over previous
#include <cuda_runtime.h>
#include <math.h>

#define EPSF 1e-9f
#define MAXF 4096
#define MAXB 8
#define FCAP 1024

// fa = (A1,B1,C1,A2), fb = (B2,C2,Az,Bz), fc = (Cz,1/z0,1/z1,1/z2), cz = Cz
// C1 NaN-poisoned when invalid/backface -> culled at the tile test, so the
// inner raster loop only ever sees finite coefficients.
__device__ float4 g_fa[MAXB * MAXF];
__device__ float4 g_fb[MAXB * MAXF];
__device__ float4 g_fc[MAXB * MAXF];
__device__ float  g_cz[MAXB * MAXF];
__device__ float4 g_tex4[MAXF * 6];
__device__ float  g_part[8192];
__device__ int    g_cnt = 0;

__global__ void prep_kernel(const float* __restrict__ verts,
                            const int*   __restrict__ faces,
                            const float* __restrict__ Kmat,
                            const float* __restrict__ Rmat,
                            const float* __restrict__ tvec,
                            const float* __restrict__ textures,
                            int B, int V, int F, int S) {
    int idx = blockIdx.x * blockDim.x + threadIdx.x;

    if (idx >= B * F) {
        // tanh threads: disjoint range [B*F, B*F + F*6)
        int ti = idx - B * F;
        if (ti < F * 6) {
            float4 v = ((const float4*)textures)[ti];
            g_tex4[ti] = make_float4(tanhf(v.x), tanhf(v.y),
                                     tanhf(v.z), tanhf(v.w));
        }
        return;
    }

    int b = idx / F;
    int f = idx - b * F;

    const float* Rb = Rmat + b * 9;
    const float* Kb = Kmat + b * 9;
    const float* tb = tvec + b * 3;

    // independent vid loads first (MLP), then vertex gathers
    int vid0 = __ldg(&faces[(b * F + f) * 3 + 0]);
    int vid1 = __ldg(&faces[(b * F + f) * 3 + 1]);
    int vid2 = __ldg(&faces[(b * F + f) * 3 + 2]);
    int vids[3] = {vid0, vid1, vid2};

    float xs[3], ys[3], zs[3];
#pragma unroll
    for (int vi = 0; vi < 3; vi++) {
        const float* p = verts + ((size_t)b * V + vids[vi]) * 3;
        float px = __ldg(p), py = __ldg(p + 1), pz = __ldg(p + 2);
        float vx = Rb[0] * px + Rb[1] * py + Rb[2] * pz + tb[0];
        float vy = Rb[3] * px + Rb[4] * py + Rb[5] * pz + tb[1];
        float vz = Rb[6] * px + Rb[7] * py + Rb[8] * pz + tb[2];
        float xh = vx / (vz + EPSF);
        float yh = vy / (vz + EPSF);
        float u  = Kb[0] * xh + Kb[1] * yh + Kb[2];
        float pv = Kb[3] * xh + Kb[4] * yh + Kb[5];
        float v  = (float)S - pv;
        u = 2.0f * (u - 0.5f * (float)S) / (float)S;
        v = 2.0f * (v - 0.5f * (float)S) / (float)S;
        xs[vi] = u; ys[vi] = v; zs[vi] = vz;
    }

    float e1x = xs[1] - xs[0], e1y = ys[1] - ys[0];
    float e2x = xs[2] - xs[0], e2y = ys[2] - ys[0];
    float den = e1x * e2y - e2x * e1y;
    bool valid = fabsf(den) > 1e-8f;
    float dens = valid ? den : 1.0f;
    bool front = fminf(zs[0], fminf(zs[1], zs[2])) > EPSF;
    float rden = 1.0f / dens;

    float A1 =  e2y * rden;
    float B1 = -e2x * rden;
    float C1 = (ys[0] * e2x - xs[0] * e2y) * rden;
    float A2 = -e1y * rden;
    float B2 =  e1x * rden;
    float C2 = (xs[0] * e1y - ys[0] * e1x) * rden;

    float iz0 = 1.0f / zs[0], iz1 = 1.0f / zs[1], iz2 = 1.0f / zs[2];
    float d1 = iz1 - iz0, d2 = iz2 - iz0;
    float Az = A1 * d1 + A2 * d2;
    float Bz = B1 * d1 + B2 * d2;
    float Cz = iz0 + C1 * d1 + C2 * d2;

    if (!(valid && front)) C1 = __int_as_float(0x7FC00000);  // NaN

    g_fa[idx] = make_float4(A1, B1, C1, A2);
    g_fb[idx] = make_float4(B2, C2, Az, Bz);
    g_fc[idx] = make_float4(Cz, iz0, iz1, iz2);
    g_cz[idx] = Cz;
}

// block (8,16,4) = 512 threads = 16 warps; tile = 16x16 px;
// each thread: 2 adjacent x-pixels, 1 of 4 face slices. 3 blocks/SM.
__global__ void __launch_bounds__(512, 3)
raster_kernel(const float* __restrict__ image_ref,
              float* __restrict__ out,
              int B, int F, int S) {
    __shared__ int    slist[FCAP];
    __shared__ float4 sa[FCAP];
    __shared__ float4 sb[FCAP];
    __shared__ float  sc[FCAP];
    __shared__ int    swcnt[16];
    __shared__ float  swred[16];
    __shared__ float  smiv[4 * 256];   // all 4 slices publish both pixels
    __shared__ int    smfc[4 * 256];
    __shared__ int    slast;

    const int b     = blockIdx.z;
    const int slice = threadIdx.z;
    const int pix   = threadIdx.y * 8 + threadIdx.x;
    const int tid   = slice * 128 + pix;
    const int warp  = tid >> 5;
    const int lane  = tid & 31;
    const int x0    = blockIdx.x * 16 + threadIdx.x * 2;
    const int y     = blockIdx.y * 16 + threadIdx.y;
    const float invS = 1.0f / (float)S;
    const float step = 2.0f * invS;
    const float py  = (2.0f * (float)y  + 1.0f - (float)S) * invS;
    const float pxA = (2.0f * (float)x0 + 1.0f - (float)S) * invS;
    const float pxB = pxA + step;

    const float cxc = (2.0f * ((float)(blockIdx.x * 16) + 7.5f) + 1.0f - (float)S) * invS;
    const float cyc = (2.0f * ((float)(blockIdx.y * 16) + 7.5f) + 1.0f - (float)S) * invS;
    const float hw  = 15.0f * invS;
    const float hh  = 15.0f * invS;

    const float4* fa_g = g_fa + (size_t)b * F;
    const float4* fb_g = g_fb + (size_t)b * F;
    const float4* fc_g = g_fc + (size_t)b * F;
    const float*  cz_g = g_cz + (size_t)b * F;

    // fused exact-halfplane cull + ordered compaction + staging (512 wide)
    int cnt = 0;
    for (int base = 0; base < F; base += 512) {
        int f = base + tid;
        bool ok = false;
        float4 fa, fb;
        if (f < F) {
            fa = fa_g[f];
            fb = fb_g[f];
            float w1c = fmaf(fa.x, cxc, fmaf(fa.y, cyc, fa.z));
            float w2c = fmaf(fa.w, cxc, fmaf(fb.x, cyc, fb.y));
            float r1  = fmaf(fabsf(fa.x), hw, fabsf(fa.y) * hh);
            float r2  = fmaf(fabsf(fa.w), hw, fabsf(fb.x) * hh);
            float a0  = fa.x + fa.w, b0 = fa.y + fb.x;
            float w0c = 1.0f - w1c - w2c;
            float r0  = fmaf(fabsf(a0), hw, fabsf(b0) * hh);
            // NaN C1 -> comparisons false -> poisoned faces never staged
            ok = (w1c + r1 >= 0.0f) && (w2c + r2 >= 0.0f) && (w0c + r0 >= 0.0f);
        }
        unsigned m = __ballot_sync(0xffffffffu, ok);
        int lanePfx = __popc(m & ((1u << lane) - 1u));
        if (lane == 0) swcnt[warp] = __popc(m);
        __syncthreads();
        int wbase = cnt;
#pragma unroll
        for (int w = 0; w < 16; w++) {
            int c = swcnt[w];
            if (w < warp) wbase += c;
            cnt += c;
        }
        if (ok) {
            int pos = wbase + lanePfx;
            slist[pos] = f;
            sa[pos] = fa;
            sb[pos] = fb;
            sc[pos] = cz_g[f];
        }
        __syncthreads();
    }
    const int nf = cnt;

    // each slice scans faces i ≡ slice (mod 4); 2 pixels per thread.
    // staged faces are all finite -> fminf inside-test is NaN-safe here.
    float bivA = EPSF, bivB = EPSF;
    int   biA = -1,   biB = -1;
#pragma unroll 4
    for (int i = slice; i < nf; i += 4) {
        const float4 fa = sa[i];
        const float4 fb = sb[i];
        const float  cz = sc[i];
        float t1 = fmaf(fa.y, py, fa.z);
        float t2 = fmaf(fb.x, py, fb.y);
        float tz = fmaf(fb.w, py, cz);
        float w1A = fmaf(fa.x, pxA, t1), w1B = fmaf(fa.x, pxB, t1);
        float w2A = fmaf(fa.w, pxA, t2), w2B = fmaf(fa.w, pxB, t2);
        float ivA = fmaf(fb.z, pxA, tz), ivB = fmaf(fb.z, pxB, tz);
        float w0A = 1.0f - w1A - w2A,    w0B = 1.0f - w1B - w2B;
        float mA = fminf(fminf(w1A, w2A), w0A);
        float mB = fminf(fminf(w1B, w2B), w0B);
        if (mA >= 0.0f && ivA > bivA) { bivA = ivA; biA = i; }
        if (mB >= 0.0f && ivB > bivB) { bivB = ivB; biB = i; }
    }
    int bfA = (biA >= 0) ? slist[biA] : -1;
    int bfB = (biB >= 0) ? slist[biB] : -1;

    // all slices publish both pixels
    {
        int o = slice * 256 + pix * 2;
        smiv[o]     = bivA; smfc[o]     = bfA;
        smiv[o + 1] = bivB; smfc[o + 1] = bfB;
    }
    __syncthreads();

    // slice0 merges pixel A, slice1 merges pixel B (deterministic:
    // max invz, ties -> smaller face id == first-index-wins argmin)
    float lsum = 0.0f;
    if (slice < 2) {
        const int sub = slice;            // 0 -> pixel A, 1 -> pixel B
        const int xx  = x0 + sub;
        const bool act = (xx < S) && (y < S);
        float biv = EPSF;
        int   bf  = -1;
#pragma unroll
        for (int s = 0; s < 4; s++) {
            int o = s * 256 + pix * 2 + sub;
            float iv = smiv[o];
            int   fc0 = smfc[o];
            if (fc0 >= 0 && (bf < 0 || iv > biv || (iv == biv && fc0 < bf))) {
                biv = iv; bf = fc0;
            }
        }

        if (act) {
            const float px = sub ? pxB : pxA;
            float col[3] = {0.0f, 0.0f, 0.0f};
            if (bf >= 0) {
                const float4 fa = fa_g[bf];
                const float4 fb = fb_g[bf];
                const float4 fc = fc_g[bf];
                float w1 = fmaf(fa.x, px, fmaf(fa.y, py, fa.z));
                float w2 = fmaf(fa.w, px, fmaf(fb.x, py, fb.y));
                float iv = fmaf(fb.z, px, fmaf(fb.w, py, fc.x));
                float w0 = 1.0f - w1 - w2;
                float iz = fmaxf(iv, EPSF);
                float r  = 1.0f / iz;
                float wp0 = __saturatef(w0 * fc.y * r);
                float wp1 = __saturatef(w1 * fc.z * r);
                float wp2 = __saturatef(w2 * fc.w * r);
                float q0 = 1.0f - wp0, q1 = 1.0f - wp1, q2 = 1.0f - wp2;
                float W[8];
                W[0] = q0 * q1 * q2;   W[1] = q0 * q1 * wp2;
                W[2] = q0 * wp1 * q2;  W[3] = q0 * wp1 * wp2;
                W[4] = wp0 * q1 * q2;  W[5] = wp0 * q1 * wp2;
                W[6] = wp0 * wp1 * q2; W[7] = wp0 * wp1 * wp2;
#pragma unroll
                for (int q = 0; q < 6; q++) {
                    float4 v = g_tex4[bf * 6 + q];
                    col[(q * 4 + 0) % 3] += v.x * W[(q * 4 + 0) / 3];
                    col[(q * 4 + 1) % 3] += v.y * W[(q * 4 + 1) / 3];
                    col[(q * 4 + 2) % 3] += v.z * W[(q * 4 + 2) / 3];
                    col[(q * 4 + 3) % 3] += v.w * W[(q * 4 + 3) / 3];
                }
            }
            float rv0 = image_ref[((size_t)(b * 3 + 0) * S + y) * S + xx];
            float rv1 = image_ref[((size_t)(b * 3 + 1) * S + y) * S + xx];
            float rv2 = image_ref[((size_t)(b * 3 + 2) * S + y) * S + xx];
            float d0 = col[0] - rv0, d1 = col[1] - rv1, d2 = col[2] - rv2;
            lsum = d0 * d0 + d1 * d1 + d2 * d2;
        }
    }

    // deterministic block reduction
#pragma unroll
    for (int o = 16; o > 0; o >>= 1)
        lsum += __shfl_down_sync(0xffffffffu, lsum, o);
    if (lane == 0) swred[warp] = lsum;
    __syncthreads();

    const int nb = gridDim.x * gridDim.y * gridDim.z;
    const int bid = blockIdx.z * gridDim.x * gridDim.y
                  + blockIdx.y * gridDim.x + blockIdx.x;
    if (tid == 0) {
        float s = 0.0f;
#pragma unroll
        for (int w = 0; w < 16; w++) s += swred[w];
        g_part[bid] = s;
        __threadfence();
        int t = atomicAdd(&g_cnt, 1);
        slast = (t == nb - 1);
    }
    __syncthreads();

    if (slast) {
        float s = 0.0f;
        for (int i = tid; i < nb; i += 512) s += g_part[i];
#pragma unroll
        for (int o = 16; o > 0; o >>= 1)
            s += __shfl_down_sync(0xffffffffu, s, o);
        if (lane == 0) swred[warp] = s;
        __syncthreads();
        if (tid == 0) {
            float tot = 0.0f;
#pragma unroll
            for (int w = 0; w < 16; w++) tot += swred[w];
            out[0] = tot;
            g_cnt = 0;   // reset for next graph replay
        }
    }
}

extern "C" void kernel_launch(void* const* d_in, const int* in_sizes, int n_in,
                              void* d_out, int out_size) {
    const float* vertices  = (const float*)d_in[0];
    const int*   faces     = (const int*)  d_in[1];
    const float* Kmat      = (const float*)d_in[2];
    const float* Rmat      = (const float*)d_in[3];
    const float* tvec      = (const float*)d_in[4];
    const float* textures  = (const float*)d_in[5];
    const float* image_ref = (const float*)d_in[6];

    int B = in_sizes[2] / 9;
    int V = in_sizes[0] / (3 * B);
    int F = in_sizes[1] / (3 * B);
    int ss = in_sizes[6] / (3 * B);
    int S = (int)(sqrt((double)ss) + 0.5);

    float* out = (float*)d_out;

    int prepN = B * F + F * 6;   // faces + tanh threads, disjoint
    prep_kernel<<<(prepN + 127) / 128, 128>>>(vertices, faces, Kmat, Rmat,
                                              tvec, textures, B, V, F, S);

    dim3 blk(8, 16, 4);
    dim3 grd((S + 15) / 16, (S + 15) / 16, B);
    raster_kernel<<<grd, blk>>>(image_ref, out, B, F, S);
}